// round 16
// baseline (speedup 1.0000x reference)
#include <cuda_runtime.h>
#include <cuda_bf16.h>
#include <math.h>
#include <stdint.h>

// Problem constants
constexpr int Bc = 2;
constexpr int Sc = 2048;
constexpr int Dc = 1024;
constexpr int Hc = 16;
constexpr int HS = 64;
constexpr int Mrows = Bc * Sc;   // 4096

// ----------------------------------------------------------------------------
// Scratch (device globals; no allocation allowed)
// ----------------------------------------------------------------------------
__device__ float g_qkv[(size_t)Mrows * 3 * Dc];
__device__ float g_rowmax[(size_t)Bc * Hc * Sc];
__device__ float g_rowsum[(size_t)Bc * Hc * Sc];
__device__ float g_attn[(size_t)Bc * Hc * Sc * Sc];

__device__ __nv_bfloat16 g_xh[(size_t)Mrows * Dc];
__device__ __nv_bfloat16 g_xl[(size_t)Mrows * Dc];
__device__ __nv_bfloat16 g_wih[(size_t)3 * Dc * Dc];
__device__ __nv_bfloat16 g_wil[(size_t)3 * Dc * Dc];
__device__ __nv_bfloat16 g_ch[(size_t)Mrows * Dc];
__device__ __nv_bfloat16 g_cl[(size_t)Mrows * Dc];
__device__ __nv_bfloat16 g_woh[(size_t)Dc * Dc];
__device__ __nv_bfloat16 g_wol[(size_t)Dc * Dc];

__device__ __nv_bfloat16 g_qkvh[(size_t)Mrows * 3 * Dc];
__device__ __nv_bfloat16 g_qkvl[(size_t)Mrows * 3 * Dc];
__device__ __nv_bfloat16 g_vth[(size_t)Bc * Hc * HS * Sc];
__device__ __nv_bfloat16 g_vtl[(size_t)Bc * Hc * HS * Sc];

// ----------------------------------------------------------------------------
// Helpers
// ----------------------------------------------------------------------------
__device__ __forceinline__ uint32_t smem_u32(const void* p) {
    uint32_t a;
    asm("{ .reg .u64 t; cvta.to.shared.u64 t, %1; cvt.u32.u64 %0, t; }" : "=r"(a) : "l"(p));
    return a;
}
#define CP_ASYNC16(dst, src) \
    asm volatile("cp.async.cg.shared.global [%0], [%1], 16;" :: "r"(dst), "l"(src) : "memory")
#define CP_COMMIT() asm volatile("cp.async.commit_group;" ::: "memory")
#define CP_WAIT(n)  asm volatile("cp.async.wait_group %0;" :: "n"(n) : "memory")

#define LDSM_X4(R, ADDR) \
    asm volatile("ldmatrix.sync.aligned.m8n8.x4.shared.b16 {%0,%1,%2,%3}, [%4];" \
        : "=r"((R)[0]), "=r"((R)[1]), "=r"((R)[2]), "=r"((R)[3]) : "r"(ADDR) : "memory")

__device__ __forceinline__ void mma16816(float* c, const uint32_t* a, const uint32_t* b) {
    asm volatile(
        "mma.sync.aligned.m16n8k16.row.col.f32.bf16.bf16.f32 "
        "{%0,%1,%2,%3}, {%4,%5,%6,%7}, {%8,%9}, {%0,%1,%2,%3};"
        : "+f"(c[0]), "+f"(c[1]), "+f"(c[2]), "+f"(c[3])
        : "r"(a[0]), "r"(a[1]), "r"(a[2]), "r"(a[3]), "r"(b[0]), "r"(b[1]));
}

__device__ __forceinline__ uint32_t pack_bf16(float a, float b) {
    __nv_bfloat162 t;
    t.x = __float2bfloat16(a);
    t.y = __float2bfloat16(b);
    return *(uint32_t*)&t;
}

// ----------------------------------------------------------------------------
// fp32 -> bf16 hi/lo split
// ----------------------------------------------------------------------------
__global__ __launch_bounds__(256) void split_bf16_kernel(
    const float4* __restrict__ src, __nv_bfloat162* __restrict__ hi,
    __nv_bfloat162* __restrict__ lo, int n4)
{
    int i = blockIdx.x * blockDim.x + threadIdx.x;
    if (i >= n4) return;
    float4 v = src[i];
    float vv[4] = {v.x, v.y, v.z, v.w};
    __nv_bfloat16 h[4], l[4];
#pragma unroll
    for (int k = 0; k < 4; ++k) {
        h[k] = __float2bfloat16(vv[k]);
        l[k] = __float2bfloat16(vv[k] - __bfloat162float(h[k]));
    }
    __nv_bfloat162 h0, h1, l0, l1;
    h0.x = h[0]; h0.y = h[1]; h1.x = h[2]; h1.y = h[3];
    l0.x = l[0]; l0.y = l[1]; l1.x = l[2]; l1.y = l[3];
    hi[i * 2 + 0] = h0; hi[i * 2 + 1] = h1;
    lo[i * 2 + 0] = l0; lo[i * 2 + 1] = l1;
}

// ----------------------------------------------------------------------------
// V transpose: qkv V region -> Vt[bh][hs][seq] bf16 hi/lo
// ----------------------------------------------------------------------------
__global__ __launch_bounds__(256) void vt_transpose_kernel(
    const float* __restrict__ qkv, __nv_bfloat16* __restrict__ vth,
    __nv_bfloat16* __restrict__ vtl)
{
    __shared__ float ts[64][65];
    const int s0 = blockIdx.x * 64;
    const int bh = blockIdx.y;
    const int b  = bh >> 4;
    const int h  = bh & 15;
    const int tid = threadIdx.x;

    const float* Vb = qkv + (size_t)b * Sc * 3072 + 2048 + h * 64;
#pragma unroll
    for (int i = 0; i < 4; ++i) {
        int idx = i * 256 + tid;
        int r = idx >> 4;
        int c4 = idx & 15;
        float4 v = *(const float4*)(Vb + (size_t)(s0 + r) * 3072 + c4 * 4);
        ts[r][c4 * 4 + 0] = v.x; ts[r][c4 * 4 + 1] = v.y;
        ts[r][c4 * 4 + 2] = v.z; ts[r][c4 * 4 + 3] = v.w;
    }
    __syncthreads();
#pragma unroll
    for (int i = 0; i < 4; ++i) {
        int idx = i * 256 + tid;
        int e  = idx >> 4;
        int sp = idx & 15;
        float f[4];
#pragma unroll
        for (int k = 0; k < 4; ++k) f[k] = ts[sp * 4 + k][e];
        __nv_bfloat16 hh[4], ll[4];
#pragma unroll
        for (int k = 0; k < 4; ++k) {
            hh[k] = __float2bfloat16(f[k]);
            ll[k] = __float2bfloat16(f[k] - __bfloat162float(hh[k]));
        }
        size_t off = (size_t)bh * HS * Sc + (size_t)e * Sc + s0 + sp * 4;
        __nv_bfloat162 p0, p1;
        p0.x = hh[0]; p0.y = hh[1]; p1.x = hh[2]; p1.y = hh[3];
        *(__nv_bfloat162*)(vth + off)     = p0;
        *(__nv_bfloat162*)(vth + off + 2) = p1;
        p0.x = ll[0]; p0.y = ll[1]; p1.x = ll[2]; p1.y = ll[3];
        *(__nv_bfloat162*)(vtl + off)     = p0;
        *(__nv_bfloat162*)(vtl + off + 2) = p1;
    }
}

// ----------------------------------------------------------------------------
// GEMM tile body (bf16x3, ldmatrix, single barrier per chunk, term-major).
// Shared by the standalone GEMM kernel and the merged outproj+norm kernel.
// ----------------------------------------------------------------------------
constexpr int HG_TILE = 128 * 40 * 2;
constexpr int HG_STAGE = 4 * HG_TILE;
constexpr int HG_SMEM  = 2 * HG_STAGE;            // 81920 B

__device__ __forceinline__ void gemm_tile_body(
    int bx, int by, char* smem,
    const __nv_bfloat16* __restrict__ Ah, const __nv_bfloat16* __restrict__ Al,
    const __nv_bfloat16* __restrict__ Wh, const __nv_bfloat16* __restrict__ Wl,
    const float* __restrict__ bias, float* __restrict__ C,
    __nv_bfloat16* __restrict__ Ch, __nv_bfloat16* __restrict__ Cl,
    int M, int N, int K)
{
    const uint32_t sb = smem_u32(smem);

    const int tid  = threadIdx.x;
    const int wid  = tid >> 5;
    const int lane = tid & 31;
    const int lr   = lane >> 2;
    const int lc   = lane & 3;
    const int q8   = lane >> 3;
    const int r8   = lane & 7;
    const int row0 = by * 128;
    const int col0 = bx * 128;
    const int m0   = (wid & 3) * 32;
    const int n0   = (wid >> 2) * 64;

    const __nv_bfloat16* srcs[4] = {Ah, Al, Wh, Wl};

    uint32_t aoff[2], boff[4];
#pragma unroll
    for (int mt = 0; mt < 2; ++mt)
        aoff[mt] = (uint32_t)((m0 + mt * 16 + (q8 & 1) * 8 + r8) * 80 + (q8 >> 1) * 16);
#pragma unroll
    for (int p = 0; p < 4; ++p)
        boff[p] = (uint32_t)((n0 + p * 16 + (q8 >> 1) * 8 + r8) * 80 + (q8 & 1) * 16);

    auto load_stage = [&](int kc, uint32_t stage) {
#pragma unroll
        for (int i = 0; i < 8; ++i) {
            int idx = i * 256 + tid;
            int t   = idx >> 9;
            int w   = idx & 511;
            int r   = w >> 2;
            int c16 = w & 3;
            int base_rc = (t < 2) ? row0 : col0;
            const void* g = (const void*)(srcs[t] + (size_t)(base_rc + r) * K + kc * 32 + c16 * 8);
            uint32_t d = stage + (uint32_t)(t * HG_TILE) + (uint32_t)(r * 80 + c16 * 16);
            CP_ASYNC16(d, g);
        }
    };

    float acc[2][8][4];
#pragma unroll
    for (int mt = 0; mt < 2; ++mt)
#pragma unroll
        for (int nt = 0; nt < 8; ++nt)
#pragma unroll
            for (int q = 0; q < 4; ++q) acc[mt][nt][q] = 0.f;

    const int NC = K >> 5;
    load_stage(0, sb);
    CP_COMMIT();

    for (int c = 0; c < NC; ++c) {
        CP_WAIT(0);
        __syncthreads();
        if (c + 1 < NC) {
            load_stage(c + 1, sb + (uint32_t)(((c + 1) & 1) * HG_STAGE));
            CP_COMMIT();
        }
        const uint32_t cur = sb + (uint32_t)((c & 1) * HG_STAGE);
        const uint32_t aH = cur;
        const uint32_t aL = cur + HG_TILE;
        const uint32_t wH = cur + 2 * HG_TILE;
        const uint32_t wL = cur + 3 * HG_TILE;

#pragma unroll
        for (int ks = 0; ks < 2; ++ks) {
            const uint32_t ko = (uint32_t)(ks * 32);
            uint32_t ah[2][4], al[2][4];
#pragma unroll
            for (int mt = 0; mt < 2; ++mt) {
                LDSM_X4(ah[mt], aH + aoff[mt] + ko);
                LDSM_X4(al[mt], aL + aoff[mt] + ko);
            }
#pragma unroll
            for (int p = 0; p < 4; ++p) {
                uint32_t bh[4], bl[4];
                LDSM_X4(bh, wH + boff[p] + ko);
                LDSM_X4(bl, wL + boff[p] + ko);
                mma16816(acc[0][2 * p],     ah[0], &bh[0]);
                mma16816(acc[0][2 * p + 1], ah[0], &bh[2]);
                mma16816(acc[1][2 * p],     ah[1], &bh[0]);
                mma16816(acc[1][2 * p + 1], ah[1], &bh[2]);
                mma16816(acc[0][2 * p],     ah[0], &bl[0]);
                mma16816(acc[0][2 * p + 1], ah[0], &bl[2]);
                mma16816(acc[1][2 * p],     ah[1], &bl[0]);
                mma16816(acc[1][2 * p + 1], ah[1], &bl[2]);
                mma16816(acc[0][2 * p],     al[0], &bh[0]);
                mma16816(acc[0][2 * p + 1], al[0], &bh[2]);
                mma16816(acc[1][2 * p],     al[1], &bh[0]);
                mma16816(acc[1][2 * p + 1], al[1], &bh[2]);
            }
        }
    }

#pragma unroll
    for (int mt = 0; mt < 2; ++mt) {
#pragma unroll
        for (int nt = 0; nt < 8; ++nt) {
            int row = row0 + m0 + mt * 16 + lr;
            int col = col0 + n0 + nt * 8 + lc * 2;
            float b0 = __ldg(&bias[col]);
            float b1 = __ldg(&bias[col + 1]);
            float v0 = acc[mt][nt][0] + b0;
            float v1 = acc[mt][nt][1] + b1;
            float v2 = acc[mt][nt][2] + b0;
            float v3 = acc[mt][nt][3] + b1;
            *(float2*)(C + (size_t)row * N + col)       = make_float2(v0, v1);
            *(float2*)(C + (size_t)(row + 8) * N + col) = make_float2(v2, v3);
            if (Ch != nullptr) {
                __nv_bfloat16 h0 = __float2bfloat16(v0), h1 = __float2bfloat16(v1);
                __nv_bfloat16 h2 = __float2bfloat16(v2), h3 = __float2bfloat16(v3);
                __nv_bfloat16 l0 = __float2bfloat16(v0 - __bfloat162float(h0));
                __nv_bfloat16 l1 = __float2bfloat16(v1 - __bfloat162float(h1));
                __nv_bfloat16 l2 = __float2bfloat16(v2 - __bfloat162float(h2));
                __nv_bfloat16 l3 = __float2bfloat16(v3 - __bfloat162float(h3));
                __nv_bfloat162 pk;
                pk.x = h0; pk.y = h1; *(__nv_bfloat162*)(Ch + (size_t)row * N + col) = pk;
                pk.x = h2; pk.y = h3; *(__nv_bfloat162*)(Ch + (size_t)(row + 8) * N + col) = pk;
                pk.x = l0; pk.y = l1; *(__nv_bfloat162*)(Cl + (size_t)row * N + col) = pk;
                pk.x = l2; pk.y = l3; *(__nv_bfloat162*)(Cl + (size_t)(row + 8) * N + col) = pk;
            }
        }
    }
}

__global__ __launch_bounds__(256, 2) void hmma_gemm_bias(
    const __nv_bfloat16* __restrict__ Ah, const __nv_bfloat16* __restrict__ Al,
    const __nv_bfloat16* __restrict__ Wh, const __nv_bfloat16* __restrict__ Wl,
    const float* __restrict__ bias, float* __restrict__ C,
    __nv_bfloat16* __restrict__ Ch, __nv_bfloat16* __restrict__ Cl,
    int M, int N, int K)
{
    extern __shared__ char smem[];
    gemm_tile_body(blockIdx.x, blockIdx.y, smem, Ah, Al, Wh, Wl, bias, C, Ch, Cl, M, N, K);
}

// ----------------------------------------------------------------------------
// Merged out-proj GEMM + softmax normalize (union grid).
// Even bids < 512 run a GEMM tile of out = ctx @ w_out^T + b (256 tiles).
// All other bids run a grid-stride slice of the normalize (2048 slices).
// The two parts are independent; complementary pipes (tensor vs DRAM) overlap.
// ----------------------------------------------------------------------------
constexpr int ON_GEMM_BLOCKS = 256;   // (Dc/128) x (Mrows/128) = 8 x 32
constexpr int ON_NORM_BLOCKS = 2048;
constexpr int ON_GRID = 2 * ON_GEMM_BLOCKS + (ON_NORM_BLOCKS - ON_GEMM_BLOCKS); // 2304

__global__ __launch_bounds__(256, 2) void outproj_norm_kernel(
    const __nv_bfloat16* __restrict__ Ah, const __nv_bfloat16* __restrict__ Al,
    const __nv_bfloat16* __restrict__ Wh, const __nv_bfloat16* __restrict__ Wl,
    const float* __restrict__ bias, float* __restrict__ C,
    float* __restrict__ attn, const float* __restrict__ rowmax,
    const float* __restrict__ rowsum)
{
    extern __shared__ char smem[];
    const int bid = blockIdx.x;

    if (bid < 2 * ON_GEMM_BLOCKS && (bid & 1) == 0) {
        const int g = bid >> 1;             // 0..255
        gemm_tile_body(g & 7, g >> 3, smem, Ah, Al, Wh, Wl, bias, C,
                       nullptr, nullptr, Mrows, Dc, Dc);
        return;
    }

    // normalize path: slice id 0..2047
    const int nb = (bid < 2 * ON_GEMM_BLOCKS) ? (bid >> 1)
                                              : (bid - ON_GEMM_BLOCKS);
    const size_t total4 = (size_t)Bc * Hc * Sc * Sc / 4;       // 33554432
    const size_t stride = (size_t)ON_NORM_BLOCKS * 256;
    for (size_t i4 = (size_t)nb * 256 + threadIdx.x; i4 < total4; i4 += stride) {
        size_t base = i4 * 4;
        int j = (int)(base & (size_t)(Sc - 1));
        size_t row = base >> 11;
        int i = (int)(row & (size_t)(Sc - 1));

        float4* p = (float4*)attn + i4;
        if (j > i) {
            *p = make_float4(0.f, 0.f, 0.f, 0.f);
            continue;
        }
        float4 v = *p;
        float mrow = rowmax[row];
        float inv  = 1.0f / rowsum[row];
        float4 o;
        o.x = (j + 0 > i) ? 0.f : __expf(v.x - mrow) * inv;
        o.y = (j + 1 > i) ? 0.f : __expf(v.y - mrow) * inv;
        o.z = (j + 2 > i) ? 0.f : __expf(v.z - mrow) * inv;
        o.w = (j + 3 > i) ? 0.f : __expf(v.w - mrow) * inv;
        *p = o;
    }
}

// ----------------------------------------------------------------------------
// FUSED flash attention (r13 version: 128-key tiles, occ 1).
// smem: Q hi/lo 36864 | K stages 2x36864 | V stages 2x34816 = 180224 B.
// ----------------------------------------------------------------------------
constexpr int FA_QL   = 18432;
constexpr int FA_K0   = 2 * FA_QL;             // 36864
constexpr int FA_KST  = 36864;
constexpr int FA_V0   = FA_K0 + 2 * FA_KST;    // 110592
constexpr int FA_VL   = 17408;                 // V operand tile (64 x 272)
constexpr int FA_VST  = 2 * FA_VL;             // 34816
constexpr int FA_SMEM = FA_V0 + 2 * FA_VST;    // 180224

__global__ __launch_bounds__(256, 1) void attn_fused_hmma(
    const __nv_bfloat16* __restrict__ qkvh, const __nv_bfloat16* __restrict__ qkvl,
    const __nv_bfloat16* __restrict__ vth, const __nv_bfloat16* __restrict__ vtl,
    float* __restrict__ attn, float* __restrict__ rowmax, float* __restrict__ rowsum,
    __nv_bfloat16* __restrict__ ch, __nv_bfloat16* __restrict__ cl)
{
    extern __shared__ char smem[];
    const uint32_t sb = smem_u32(smem);
    const int qt = blockIdx.x;
    const int bh = blockIdx.y;
    const int b  = bh >> 4;
    const int h  = bh & 15;
    const int tid = threadIdx.x, w = tid >> 5, lane = tid & 31;
    const int lr = lane >> 2, lc = lane & 3;
    const int q8 = lane >> 3, r8 = lane & 7;

    const __nv_bfloat16* Qh = qkvh + (size_t)b * Sc * 3072 + (size_t)qt * 128 * 3072 + h * 64;
    const __nv_bfloat16* Ql = qkvl + (size_t)b * Sc * 3072 + (size_t)qt * 128 * 3072 + h * 64;
    const __nv_bfloat16* Kh = qkvh + (size_t)b * Sc * 3072 + 1024 + h * 64;
    const __nv_bfloat16* Kl = qkvl + (size_t)b * Sc * 3072 + 1024 + h * 64;
    const __nv_bfloat16* Vh = vth + (size_t)bh * HS * Sc;
    const __nv_bfloat16* Vl = vtl + (size_t)bh * HS * Sc;
    float* attn_bh = attn + (size_t)bh * Sc * Sc;

#pragma unroll
    for (int i = 0; i < 8; ++i) {
        int idx = i * 256 + tid;
        int op = idx >> 10;
        int ww = idx & 1023;
        int r = ww >> 3, c = ww & 7;
        const void* g = (const void*)((op ? Ql : Qh) + (size_t)r * 3072 + c * 8);
        CP_ASYNC16(sb + (uint32_t)(op * FA_QL) + (uint32_t)(r * 144 + c * 16), g);
    }
    auto load_kv = [&](int kt, int st) {
        uint32_t kbase = sb + FA_K0 + (uint32_t)(st * FA_KST);
#pragma unroll
        for (int i = 0; i < 8; ++i) {
            int idx = i * 256 + tid;
            int op = idx >> 10;
            int ww = idx & 1023;
            int r = ww >> 3, c = ww & 7;
            const void* g = (const void*)((op ? Kl : Kh) + (size_t)(kt * 128 + r) * 3072 + c * 8);
            CP_ASYNC16(kbase + (uint32_t)(op * FA_QL) + (uint32_t)(r * 144 + c * 16), g);
        }
        uint32_t vbase = sb + FA_V0 + (uint32_t)(st * FA_VST);
#pragma unroll
        for (int i = 0; i < 8; ++i) {
            int idx = i * 256 + tid;
            int op = idx >> 10;
            int ww = idx & 1023;
            int r = ww >> 4, c16 = ww & 15;
            const void* g = (const void*)((op ? Vl : Vh) + (size_t)r * Sc + kt * 128 + c16 * 8);
            CP_ASYNC16(vbase + (uint32_t)(op * FA_VL) + (uint32_t)(r * 272 + c16 * 16), g);
        }
    };
    load_kv(0, 0);
    CP_COMMIT();

    float m_run[2] = {-INFINITY, -INFINITY};
    float s_run[2] = {0.f, 0.f};

    float outacc[8][4];
#pragma unroll
    for (int nt = 0; nt < 8; ++nt)
#pragma unroll
        for (int q = 0; q < 4; ++q) outacc[nt][q] = 0.f;

    const uint32_t qoff = (uint32_t)((w * 16 + (q8 & 1) * 8 + r8) * 144 + (q8 >> 1) * 16);
    uint32_t koffs[8];
#pragma unroll
    for (int p = 0; p < 8; ++p)
        koffs[p] = (uint32_t)((p * 16 + (q8 >> 1) * 8 + r8) * 144 + (q8 & 1) * 16);
    uint32_t voffs[4];
#pragma unroll
    for (int p = 0; p < 4; ++p)
        voffs[p] = (uint32_t)((p * 16 + (q8 >> 1) * 8 + r8) * 272 + (q8 & 1) * 16);

    for (int kt = 0; kt <= qt; ++kt) {
        CP_WAIT(0);
        __syncthreads();
        if (kt < qt) {
            load_kv(kt + 1, (kt + 1) & 1);
            CP_COMMIT();
        }

        const uint32_t kbh = sb + FA_K0 + (uint32_t)((kt & 1) * FA_KST);
        const uint32_t kbl = kbh + FA_QL;

        float acc[16][4];
#pragma unroll
        for (int nt = 0; nt < 16; ++nt)
#pragma unroll
            for (int q = 0; q < 4; ++q) acc[nt][q] = 0.f;

#pragma unroll
        for (int ks = 0; ks < 4; ++ks) {
            const uint32_t ko = (uint32_t)(ks * 32);
            uint32_t ah[4], al[4];
            LDSM_X4(ah, sb + qoff + ko);
            LDSM_X4(al, sb + FA_QL + qoff + ko);
#pragma unroll
            for (int p = 0; p < 8; ++p) {
                uint32_t bhf[4], blf[4];
                LDSM_X4(bhf, kbh + koffs[p] + ko);
                LDSM_X4(blf, kbl + koffs[p] + ko);
                mma16816(acc[2 * p],     ah, &bhf[0]);
                mma16816(acc[2 * p + 1], ah, &bhf[2]);
                mma16816(acc[2 * p],     ah, &blf[0]);
                mma16816(acc[2 * p + 1], ah, &blf[2]);
                mma16816(acc[2 * p],     al, &bhf[0]);
                mma16816(acc[2 * p + 1], al, &bhf[2]);
            }
        }

        const bool diag = (kt == qt);
        const int r0 = w * 16 + lr;
#pragma unroll
        for (int nt = 0; nt < 16; ++nt) {
#pragma unroll
            for (int q = 0; q < 4; ++q) {
                float v = acc[nt][q] * 0.125f;
                if (diag) {
                    int rl = r0 + ((q >= 2) ? 8 : 0);
                    int cl2 = nt * 8 + lc * 2 + (q & 1);
                    if (cl2 > rl) v = -INFINITY;
                }
                acc[nt][q] = v;
            }
            float* p0 = attn_bh + (size_t)(qt * 128 + r0) * Sc + kt * 128 + nt * 8 + lc * 2;
            *(float2*)p0 = make_float2(acc[nt][0], acc[nt][1]);
            *(float2*)(p0 + 8 * Sc) = make_float2(acc[nt][2], acc[nt][3]);
        }

        float nmr[2], fr[2];
#pragma unroll
        for (int r = 0; r < 2; ++r) {
            float tm = -INFINITY;
#pragma unroll
            for (int nt = 0; nt < 16; ++nt)
                tm = fmaxf(tm, fmaxf(acc[nt][r * 2], acc[nt][r * 2 + 1]));
            tm = fmaxf(tm, __shfl_xor_sync(0xffffffffu, tm, 1));
            tm = fmaxf(tm, __shfl_xor_sync(0xffffffffu, tm, 2));
            float nm = fmaxf(m_run[r], tm);
            nmr[r] = nm;
            fr[r]  = __expf(m_run[r] - nm);
            m_run[r] = nm;
        }
#pragma unroll
        for (int nt = 0; nt < 8; ++nt) {
            outacc[nt][0] *= fr[0]; outacc[nt][1] *= fr[0];
            outacc[nt][2] *= fr[1]; outacc[nt][3] *= fr[1];
        }
#pragma unroll
        for (int nt = 0; nt < 16; ++nt) {
            acc[nt][0] = __expf(acc[nt][0] - nmr[0]);
            acc[nt][1] = __expf(acc[nt][1] - nmr[0]);
            acc[nt][2] = __expf(acc[nt][2] - nmr[1]);
            acc[nt][3] = __expf(acc[nt][3] - nmr[1]);
        }
#pragma unroll
        for (int r = 0; r < 2; ++r) {
            float sl = 0.f;
#pragma unroll
            for (int nt = 0; nt < 16; ++nt)
                sl += acc[nt][r * 2] + acc[nt][r * 2 + 1];
            sl += __shfl_xor_sync(0xffffffffu, sl, 1);
            sl += __shfl_xor_sync(0xffffffffu, sl, 2);
            s_run[r] = s_run[r] * fr[r] + sl;
        }

        const uint32_t vHb = sb + FA_V0 + (uint32_t)((kt & 1) * FA_VST);
        const uint32_t vLb = vHb + FA_VL;
#pragma unroll
        for (int ks = 0; ks < 8; ++ks) {
            uint32_t pa_h[4], pa_l[4];
            const float* A0 = acc[2 * ks];
            const float* A1 = acc[2 * ks + 1];
            pa_h[0] = pack_bf16(A0[0], A0[1]);
            pa_h[1] = pack_bf16(A0[2], A0[3]);
            pa_h[2] = pack_bf16(A1[0], A1[1]);
            pa_h[3] = pack_bf16(A1[2], A1[3]);
            {
                __nv_bfloat162 t0 = *(__nv_bfloat162*)&pa_h[0];
                __nv_bfloat162 t1 = *(__nv_bfloat162*)&pa_h[1];
                __nv_bfloat162 t2 = *(__nv_bfloat162*)&pa_h[2];
                __nv_bfloat162 t3 = *(__nv_bfloat162*)&pa_h[3];
                pa_l[0] = pack_bf16(A0[0] - __bfloat162float(t0.x), A0[1] - __bfloat162float(t0.y));
                pa_l[1] = pack_bf16(A0[2] - __bfloat162float(t1.x), A0[3] - __bfloat162float(t1.y));
                pa_l[2] = pack_bf16(A1[0] - __bfloat162float(t2.x), A1[1] - __bfloat162float(t2.y));
                pa_l[3] = pack_bf16(A1[2] - __bfloat162float(t3.x), A1[3] - __bfloat162float(t3.y));
            }
            const uint32_t kov = (uint32_t)(ks * 32);
#pragma unroll
            for (int p = 0; p < 4; ++p) {
                uint32_t vh4[4], vl4[4];
                LDSM_X4(vh4, vHb + voffs[p] + kov);
                LDSM_X4(vl4, vLb + voffs[p] + kov);
                mma16816(outacc[2 * p],     pa_h, &vh4[0]);
                mma16816(outacc[2 * p + 1], pa_h, &vh4[2]);
                mma16816(outacc[2 * p],     pa_h, &vl4[0]);
                mma16816(outacc[2 * p + 1], pa_h, &vl4[2]);
                mma16816(outacc[2 * p],     pa_l, &vh4[0]);
                mma16816(outacc[2 * p + 1], pa_l, &vh4[2]);
            }
        }
    }

    if (lc == 0) {
        int gi0 = qt * 128 + w * 16 + lr;
        rowmax[(size_t)bh * Sc + gi0]     = m_run[0];
        rowsum[(size_t)bh * Sc + gi0]     = s_run[0];
        rowmax[(size_t)bh * Sc + gi0 + 8] = m_run[1];
        rowsum[(size_t)bh * Sc + gi0 + 8] = s_run[1];
    }

    const float inv0 = 1.0f / s_run[0];
    const float inv1 = 1.0f / s_run[1];
#pragma unroll
    for (int nt = 0; nt < 8; ++nt) {
        int gi = qt * 128 + w * 16 + lr;
        size_t base0 = ((size_t)b * Sc + gi) * Dc + h * HS + nt * 8 + lc * 2;
        float v0 = outacc[nt][0] * inv0;
        float v1 = outacc[nt][1] * inv0;
        float v2 = outacc[nt][2] * inv1;
        float v3 = outacc[nt][3] * inv1;
        __nv_bfloat16 h0 = __float2bfloat16(v0);
        __nv_bfloat16 h1 = __float2bfloat16(v1);
        __nv_bfloat16 h2 = __float2bfloat16(v2);
        __nv_bfloat16 h3 = __float2bfloat16(v3);
        __nv_bfloat16 l0 = __float2bfloat16(v0 - __bfloat162float(h0));
        __nv_bfloat16 l1 = __float2bfloat16(v1 - __bfloat162float(h1));
        __nv_bfloat16 l2 = __float2bfloat16(v2 - __bfloat162float(h2));
        __nv_bfloat16 l3 = __float2bfloat16(v3 - __bfloat162float(h3));
        __nv_bfloat162 hp, lp;
        hp.x = h0; hp.y = h1; lp.x = l0; lp.y = l1;
        *(__nv_bfloat162*)(ch + base0) = hp;
        *(__nv_bfloat162*)(cl + base0) = lp;
        hp.x = h2; hp.y = h3; lp.x = l2; lp.y = l3;
        *(__nv_bfloat162*)(ch + base0 + (size_t)8 * Dc) = hp;
        *(__nv_bfloat162*)(cl + base0 + (size_t)8 * Dc) = lp;
    }
}

// ----------------------------------------------------------------------------
// Launch
// ----------------------------------------------------------------------------
extern "C" void kernel_launch(void* const* d_in, const int* in_sizes, int n_in,
                              void* d_out, int out_size)
{
    const float* x     = (const float*)d_in[0];
    const float* w_in  = (const float*)d_in[1];
    const float* b_in  = (const float*)d_in[2];
    const float* w_out = (const float*)d_in[3];
    const float* b_out = (const float*)d_in[4];
    float* out = (float*)d_out;

    float *qkv, *rmax, *rsum, *attn_scratch;
    cudaGetSymbolAddress((void**)&qkv,  g_qkv);
    cudaGetSymbolAddress((void**)&rmax, g_rowmax);
    cudaGetSymbolAddress((void**)&rsum, g_rowsum);
    cudaGetSymbolAddress((void**)&attn_scratch, g_attn);

    __nv_bfloat16 *xh, *xl, *wih, *wil, *ch, *cl, *woh, *wol;
    __nv_bfloat16 *qkvh, *qkvl, *vth, *vtl;
    cudaGetSymbolAddress((void**)&xh,  g_xh);
    cudaGetSymbolAddress((void**)&xl,  g_xl);
    cudaGetSymbolAddress((void**)&wih, g_wih);
    cudaGetSymbolAddress((void**)&wil, g_wil);
    cudaGetSymbolAddress((void**)&ch,  g_ch);
    cudaGetSymbolAddress((void**)&cl,  g_cl);
    cudaGetSymbolAddress((void**)&woh, g_woh);
    cudaGetSymbolAddress((void**)&wol, g_wol);
    cudaGetSymbolAddress((void**)&qkvh, g_qkvh);
    cudaGetSymbolAddress((void**)&qkvl, g_qkvl);
    cudaGetSymbolAddress((void**)&vth, g_vth);
    cudaGetSymbolAddress((void**)&vtl, g_vtl);

    const size_t out_elems  = (size_t)Bc * Sc * Dc;
    const size_t attn_elems = (size_t)Bc * Hc * Sc * Sc;
    float* attn = ((size_t)out_size >= out_elems + attn_elems) ? (out + out_elems)
                                                               : attn_scratch;

    cudaFuncSetAttribute(hmma_gemm_bias, cudaFuncAttributeMaxDynamicSharedMemorySize, HG_SMEM);
    cudaFuncSetAttribute(outproj_norm_kernel, cudaFuncAttributeMaxDynamicSharedMemorySize, HG_SMEM);
    cudaFuncSetAttribute(attn_fused_hmma, cudaFuncAttributeMaxDynamicSharedMemorySize, FA_SMEM);

    // Splits of inputs
    {
        int n4 = (Mrows * Dc) / 4;
        split_bf16_kernel<<<(n4 + 255) / 256, 256>>>((const float4*)x,
            (__nv_bfloat162*)xh, (__nv_bfloat162*)xl, n4);
        n4 = (3 * Dc * Dc) / 4;
        split_bf16_kernel<<<(n4 + 255) / 256, 256>>>((const float4*)w_in,
            (__nv_bfloat162*)wih, (__nv_bfloat162*)wil, n4);
        n4 = (Dc * Dc) / 4;
        split_bf16_kernel<<<(n4 + 255) / 256, 256>>>((const float4*)w_out,
            (__nv_bfloat162*)woh, (__nv_bfloat162*)wol, n4);
    }

    // 1) QKV projection (epilogue emits qkvh/qkvl)
    {
        dim3 g((3 * Dc) / 128, Mrows / 128);
        hmma_gemm_bias<<<g, 256, HG_SMEM>>>(xh, xl, wih, wil, b_in, qkv,
                                            qkvh, qkvl, Mrows, 3 * Dc, Dc);
    }

    // 2) Transpose V
    {
        dim3 gt(Sc / 64, Bc * Hc);
        vt_transpose_kernel<<<gt, 256>>>(qkv, vth, vtl);
    }

    // 3) Fused flash attention: raw attn, (m,s), ch/cl
    dim3 g2(Sc / 128, Bc * Hc);
    attn_fused_hmma<<<g2, 256, FA_SMEM>>>(qkvh, qkvl, vth, vtl,
                                          attn, rmax, rsum, ch, cl);

    // 4) Merged: output projection + softmax normalize (overlapped union grid)
    outproj_norm_kernel<<<ON_GRID, 256, HG_SMEM>>>(ch, cl, woh, wol, b_out, out,
                                                   attn, rmax, rsum);
}

// round 17
// speedup vs baseline: 1.1531x; 1.1531x over previous
#include <cuda_runtime.h>
#include <cuda_bf16.h>
#include <math.h>
#include <stdint.h>

// Problem constants
constexpr int Bc = 2;
constexpr int Sc = 2048;
constexpr int Dc = 1024;
constexpr int Hc = 16;
constexpr int HS = 64;
constexpr int Mrows = Bc * Sc;   // 4096

// ----------------------------------------------------------------------------
// Scratch (device globals; no allocation allowed)
// ----------------------------------------------------------------------------
__device__ float g_qkv[(size_t)Mrows * 3 * Dc];
__device__ float g_rowmax[(size_t)Bc * Hc * Sc];
__device__ float g_rowsum[(size_t)Bc * Hc * Sc];
__device__ float g_attn[(size_t)Bc * Hc * Sc * Sc];

__device__ __nv_bfloat16 g_xh[(size_t)Mrows * Dc];
__device__ __nv_bfloat16 g_xl[(size_t)Mrows * Dc];
__device__ __nv_bfloat16 g_wih[(size_t)3 * Dc * Dc];
__device__ __nv_bfloat16 g_wil[(size_t)3 * Dc * Dc];
__device__ __nv_bfloat16 g_ch[(size_t)Mrows * Dc];
__device__ __nv_bfloat16 g_cl[(size_t)Mrows * Dc];
__device__ __nv_bfloat16 g_woh[(size_t)Dc * Dc];
__device__ __nv_bfloat16 g_wol[(size_t)Dc * Dc];

__device__ __nv_bfloat16 g_qkvh[(size_t)Mrows * 3 * Dc];
__device__ __nv_bfloat16 g_qkvl[(size_t)Mrows * 3 * Dc];
__device__ __nv_bfloat16 g_vth[(size_t)Bc * Hc * HS * Sc];
__device__ __nv_bfloat16 g_vtl[(size_t)Bc * Hc * HS * Sc];

// ----------------------------------------------------------------------------
// Helpers
// ----------------------------------------------------------------------------
__device__ __forceinline__ uint32_t smem_u32(const void* p) {
    uint32_t a;
    asm("{ .reg .u64 t; cvta.to.shared.u64 t, %1; cvt.u32.u64 %0, t; }" : "=r"(a) : "l"(p));
    return a;
}
#define CP_ASYNC16(dst, src) \
    asm volatile("cp.async.cg.shared.global [%0], [%1], 16;" :: "r"(dst), "l"(src) : "memory")
#define CP_COMMIT() asm volatile("cp.async.commit_group;" ::: "memory")
#define CP_WAIT(n)  asm volatile("cp.async.wait_group %0;" :: "n"(n) : "memory")

#define LDSM_X4(R, ADDR) \
    asm volatile("ldmatrix.sync.aligned.m8n8.x4.shared.b16 {%0,%1,%2,%3}, [%4];" \
        : "=r"((R)[0]), "=r"((R)[1]), "=r"((R)[2]), "=r"((R)[3]) : "r"(ADDR) : "memory")

__device__ __forceinline__ void mma16816(float* c, const uint32_t* a, const uint32_t* b) {
    asm volatile(
        "mma.sync.aligned.m16n8k16.row.col.f32.bf16.bf16.f32 "
        "{%0,%1,%2,%3}, {%4,%5,%6,%7}, {%8,%9}, {%0,%1,%2,%3};"
        : "+f"(c[0]), "+f"(c[1]), "+f"(c[2]), "+f"(c[3])
        : "r"(a[0]), "r"(a[1]), "r"(a[2]), "r"(a[3]), "r"(b[0]), "r"(b[1]));
}

__device__ __forceinline__ uint32_t pack_bf16(float a, float b) {
    __nv_bfloat162 t;
    t.x = __float2bfloat16(a);
    t.y = __float2bfloat16(b);
    return *(uint32_t*)&t;
}

// ----------------------------------------------------------------------------
// fp32 -> bf16 hi/lo split
// ----------------------------------------------------------------------------
__global__ __launch_bounds__(256) void split_bf16_kernel(
    const float4* __restrict__ src, __nv_bfloat162* __restrict__ hi,
    __nv_bfloat162* __restrict__ lo, int n4)
{
    int i = blockIdx.x * blockDim.x + threadIdx.x;
    if (i >= n4) return;
    float4 v = src[i];
    float vv[4] = {v.x, v.y, v.z, v.w};
    __nv_bfloat16 h[4], l[4];
#pragma unroll
    for (int k = 0; k < 4; ++k) {
        h[k] = __float2bfloat16(vv[k]);
        l[k] = __float2bfloat16(vv[k] - __bfloat162float(h[k]));
    }
    __nv_bfloat162 h0, h1, l0, l1;
    h0.x = h[0]; h0.y = h[1]; h1.x = h[2]; h1.y = h[3];
    l0.x = l[0]; l0.y = l[1]; l1.x = l[2]; l1.y = l[3];
    hi[i * 2 + 0] = h0; hi[i * 2 + 1] = h1;
    lo[i * 2 + 0] = l0; lo[i * 2 + 1] = l1;
}

// ----------------------------------------------------------------------------
// V transpose: qkv V region -> Vt[bh][hs][seq] bf16 hi/lo
// ----------------------------------------------------------------------------
__global__ __launch_bounds__(256) void vt_transpose_kernel(
    const float* __restrict__ qkv, __nv_bfloat16* __restrict__ vth,
    __nv_bfloat16* __restrict__ vtl)
{
    __shared__ float ts[64][65];
    const int s0 = blockIdx.x * 64;
    const int bh = blockIdx.y;
    const int b  = bh >> 4;
    const int h  = bh & 15;
    const int tid = threadIdx.x;

    const float* Vb = qkv + (size_t)b * Sc * 3072 + 2048 + h * 64;
#pragma unroll
    for (int i = 0; i < 4; ++i) {
        int idx = i * 256 + tid;
        int r = idx >> 4;
        int c4 = idx & 15;
        float4 v = *(const float4*)(Vb + (size_t)(s0 + r) * 3072 + c4 * 4);
        ts[r][c4 * 4 + 0] = v.x; ts[r][c4 * 4 + 1] = v.y;
        ts[r][c4 * 4 + 2] = v.z; ts[r][c4 * 4 + 3] = v.w;
    }
    __syncthreads();
#pragma unroll
    for (int i = 0; i < 4; ++i) {
        int idx = i * 256 + tid;
        int e  = idx >> 4;
        int sp = idx & 15;
        float f[4];
#pragma unroll
        for (int k = 0; k < 4; ++k) f[k] = ts[sp * 4 + k][e];
        __nv_bfloat16 hh[4], ll[4];
#pragma unroll
        for (int k = 0; k < 4; ++k) {
            hh[k] = __float2bfloat16(f[k]);
            ll[k] = __float2bfloat16(f[k] - __bfloat162float(hh[k]));
        }
        size_t off = (size_t)bh * HS * Sc + (size_t)e * Sc + s0 + sp * 4;
        __nv_bfloat162 p0, p1;
        p0.x = hh[0]; p0.y = hh[1]; p1.x = hh[2]; p1.y = hh[3];
        *(__nv_bfloat162*)(vth + off)     = p0;
        *(__nv_bfloat162*)(vth + off + 2) = p1;
        p0.x = ll[0]; p0.y = ll[1]; p1.x = ll[2]; p1.y = ll[3];
        *(__nv_bfloat162*)(vtl + off)     = p0;
        *(__nv_bfloat162*)(vtl + off + 2) = p1;
    }
}

// ----------------------------------------------------------------------------
// HMMA bf16x3 GEMM (128x128, occ 2, single barrier, term-major).
// ----------------------------------------------------------------------------
constexpr int HG_TILE = 128 * 40 * 2;
constexpr int HG_STAGE = 4 * HG_TILE;
constexpr int HG_SMEM  = 2 * HG_STAGE;            // 81920 B

__global__ __launch_bounds__(256, 2) void hmma_gemm_bias(
    const __nv_bfloat16* __restrict__ Ah, const __nv_bfloat16* __restrict__ Al,
    const __nv_bfloat16* __restrict__ Wh, const __nv_bfloat16* __restrict__ Wl,
    const float* __restrict__ bias, float* __restrict__ C,
    __nv_bfloat16* __restrict__ Ch, __nv_bfloat16* __restrict__ Cl,
    int M, int N, int K)
{
    extern __shared__ char smem[];
    const uint32_t sb = smem_u32(smem);

    const int tid  = threadIdx.x;
    const int wid  = tid >> 5;
    const int lane = tid & 31;
    const int lr   = lane >> 2;
    const int lc   = lane & 3;
    const int q8   = lane >> 3;
    const int r8   = lane & 7;
    const int row0 = blockIdx.y * 128;
    const int col0 = blockIdx.x * 128;
    const int m0   = (wid & 3) * 32;
    const int n0   = (wid >> 2) * 64;

    const __nv_bfloat16* srcs[4] = {Ah, Al, Wh, Wl};

    uint32_t aoff[2], boff[4];
#pragma unroll
    for (int mt = 0; mt < 2; ++mt)
        aoff[mt] = (uint32_t)((m0 + mt * 16 + (q8 & 1) * 8 + r8) * 80 + (q8 >> 1) * 16);
#pragma unroll
    for (int p = 0; p < 4; ++p)
        boff[p] = (uint32_t)((n0 + p * 16 + (q8 >> 1) * 8 + r8) * 80 + (q8 & 1) * 16);

    auto load_stage = [&](int kc, uint32_t stage) {
#pragma unroll
        for (int i = 0; i < 8; ++i) {
            int idx = i * 256 + tid;
            int t   = idx >> 9;
            int w   = idx & 511;
            int r   = w >> 2;
            int c16 = w & 3;
            int base_rc = (t < 2) ? row0 : col0;
            const void* g = (const void*)(srcs[t] + (size_t)(base_rc + r) * K + kc * 32 + c16 * 8);
            uint32_t d = stage + (uint32_t)(t * HG_TILE) + (uint32_t)(r * 80 + c16 * 16);
            CP_ASYNC16(d, g);
        }
    };

    float acc[2][8][4];
#pragma unroll
    for (int mt = 0; mt < 2; ++mt)
#pragma unroll
        for (int nt = 0; nt < 8; ++nt)
#pragma unroll
            for (int q = 0; q < 4; ++q) acc[mt][nt][q] = 0.f;

    const int NC = K >> 5;
    load_stage(0, sb);
    CP_COMMIT();

    for (int c = 0; c < NC; ++c) {
        CP_WAIT(0);
        __syncthreads();
        if (c + 1 < NC) {
            load_stage(c + 1, sb + (uint32_t)(((c + 1) & 1) * HG_STAGE));
            CP_COMMIT();
        }
        const uint32_t cur = sb + (uint32_t)((c & 1) * HG_STAGE);
        const uint32_t aH = cur;
        const uint32_t aL = cur + HG_TILE;
        const uint32_t wH = cur + 2 * HG_TILE;
        const uint32_t wL = cur + 3 * HG_TILE;

#pragma unroll
        for (int ks = 0; ks < 2; ++ks) {
            const uint32_t ko = (uint32_t)(ks * 32);
            uint32_t ah[2][4], al[2][4];
#pragma unroll
            for (int mt = 0; mt < 2; ++mt) {
                LDSM_X4(ah[mt], aH + aoff[mt] + ko);
                LDSM_X4(al[mt], aL + aoff[mt] + ko);
            }
#pragma unroll
            for (int p = 0; p < 4; ++p) {
                uint32_t bh[4], bl[4];
                LDSM_X4(bh, wH + boff[p] + ko);
                LDSM_X4(bl, wL + boff[p] + ko);
                mma16816(acc[0][2 * p],     ah[0], &bh[0]);
                mma16816(acc[0][2 * p + 1], ah[0], &bh[2]);
                mma16816(acc[1][2 * p],     ah[1], &bh[0]);
                mma16816(acc[1][2 * p + 1], ah[1], &bh[2]);
                mma16816(acc[0][2 * p],     ah[0], &bl[0]);
                mma16816(acc[0][2 * p + 1], ah[0], &bl[2]);
                mma16816(acc[1][2 * p],     ah[1], &bl[0]);
                mma16816(acc[1][2 * p + 1], ah[1], &bl[2]);
                mma16816(acc[0][2 * p],     al[0], &bh[0]);
                mma16816(acc[0][2 * p + 1], al[0], &bh[2]);
                mma16816(acc[1][2 * p],     al[1], &bh[0]);
                mma16816(acc[1][2 * p + 1], al[1], &bh[2]);
            }
        }
    }

#pragma unroll
    for (int mt = 0; mt < 2; ++mt) {
#pragma unroll
        for (int nt = 0; nt < 8; ++nt) {
            int row = row0 + m0 + mt * 16 + lr;
            int col = col0 + n0 + nt * 8 + lc * 2;
            float b0 = __ldg(&bias[col]);
            float b1 = __ldg(&bias[col + 1]);
            float v0 = acc[mt][nt][0] + b0;
            float v1 = acc[mt][nt][1] + b1;
            float v2 = acc[mt][nt][2] + b0;
            float v3 = acc[mt][nt][3] + b1;
            *(float2*)(C + (size_t)row * N + col)       = make_float2(v0, v1);
            *(float2*)(C + (size_t)(row + 8) * N + col) = make_float2(v2, v3);
            if (Ch != nullptr) {
                __nv_bfloat16 h0 = __float2bfloat16(v0), h1 = __float2bfloat16(v1);
                __nv_bfloat16 h2 = __float2bfloat16(v2), h3 = __float2bfloat16(v3);
                __nv_bfloat16 l0 = __float2bfloat16(v0 - __bfloat162float(h0));
                __nv_bfloat16 l1 = __float2bfloat16(v1 - __bfloat162float(h1));
                __nv_bfloat16 l2 = __float2bfloat16(v2 - __bfloat162float(h2));
                __nv_bfloat16 l3 = __float2bfloat16(v3 - __bfloat162float(h3));
                __nv_bfloat162 pk;
                pk.x = h0; pk.y = h1; *(__nv_bfloat162*)(Ch + (size_t)row * N + col) = pk;
                pk.x = h2; pk.y = h3; *(__nv_bfloat162*)(Ch + (size_t)(row + 8) * N + col) = pk;
                pk.x = l0; pk.y = l1; *(__nv_bfloat162*)(Cl + (size_t)row * N + col) = pk;
                pk.x = l2; pk.y = l3; *(__nv_bfloat162*)(Cl + (size_t)(row + 8) * N + col) = pk;
            }
        }
    }
}

// ----------------------------------------------------------------------------
// FUSED flash attention (r13: 128-key tiles, occ 1).
// smem: Q hi/lo 36864 | K stages 2x36864 | V stages 2x34816 = 180224 B.
// ----------------------------------------------------------------------------
constexpr int FA_QL   = 18432;
constexpr int FA_K0   = 2 * FA_QL;             // 36864
constexpr int FA_KST  = 36864;
constexpr int FA_V0   = FA_K0 + 2 * FA_KST;    // 110592
constexpr int FA_VL   = 17408;                 // V operand tile (64 x 272)
constexpr int FA_VST  = 2 * FA_VL;             // 34816
constexpr int FA_SMEM = FA_V0 + 2 * FA_VST;    // 180224

__global__ __launch_bounds__(256, 1) void attn_fused_hmma(
    const __nv_bfloat16* __restrict__ qkvh, const __nv_bfloat16* __restrict__ qkvl,
    const __nv_bfloat16* __restrict__ vth, const __nv_bfloat16* __restrict__ vtl,
    float* __restrict__ attn, float* __restrict__ rowmax, float* __restrict__ rowsum,
    __nv_bfloat16* __restrict__ ch, __nv_bfloat16* __restrict__ cl)
{
    extern __shared__ char smem[];
    const uint32_t sb = smem_u32(smem);
    const int qt = blockIdx.x;
    const int bh = blockIdx.y;
    const int b  = bh >> 4;
    const int h  = bh & 15;
    const int tid = threadIdx.x, w = tid >> 5, lane = tid & 31;
    const int lr = lane >> 2, lc = lane & 3;
    const int q8 = lane >> 3, r8 = lane & 7;

    const __nv_bfloat16* Qh = qkvh + (size_t)b * Sc * 3072 + (size_t)qt * 128 * 3072 + h * 64;
    const __nv_bfloat16* Ql = qkvl + (size_t)b * Sc * 3072 + (size_t)qt * 128 * 3072 + h * 64;
    const __nv_bfloat16* Kh = qkvh + (size_t)b * Sc * 3072 + 1024 + h * 64;
    const __nv_bfloat16* Kl = qkvl + (size_t)b * Sc * 3072 + 1024 + h * 64;
    const __nv_bfloat16* Vh = vth + (size_t)bh * HS * Sc;
    const __nv_bfloat16* Vl = vtl + (size_t)bh * HS * Sc;
    float* attn_bh = attn + (size_t)bh * Sc * Sc;

#pragma unroll
    for (int i = 0; i < 8; ++i) {
        int idx = i * 256 + tid;
        int op = idx >> 10;
        int ww = idx & 1023;
        int r = ww >> 3, c = ww & 7;
        const void* g = (const void*)((op ? Ql : Qh) + (size_t)r * 3072 + c * 8);
        CP_ASYNC16(sb + (uint32_t)(op * FA_QL) + (uint32_t)(r * 144 + c * 16), g);
    }
    auto load_kv = [&](int kt, int st) {
        uint32_t kbase = sb + FA_K0 + (uint32_t)(st * FA_KST);
#pragma unroll
        for (int i = 0; i < 8; ++i) {
            int idx = i * 256 + tid;
            int op = idx >> 10;
            int ww = idx & 1023;
            int r = ww >> 3, c = ww & 7;
            const void* g = (const void*)((op ? Kl : Kh) + (size_t)(kt * 128 + r) * 3072 + c * 8);
            CP_ASYNC16(kbase + (uint32_t)(op * FA_QL) + (uint32_t)(r * 144 + c * 16), g);
        }
        uint32_t vbase = sb + FA_V0 + (uint32_t)(st * FA_VST);
#pragma unroll
        for (int i = 0; i < 8; ++i) {
            int idx = i * 256 + tid;
            int op = idx >> 10;
            int ww = idx & 1023;
            int r = ww >> 4, c16 = ww & 15;
            const void* g = (const void*)((op ? Vl : Vh) + (size_t)r * Sc + kt * 128 + c16 * 8);
            CP_ASYNC16(vbase + (uint32_t)(op * FA_VL) + (uint32_t)(r * 272 + c16 * 16), g);
        }
    };
    load_kv(0, 0);
    CP_COMMIT();

    float m_run[2] = {-INFINITY, -INFINITY};
    float s_run[2] = {0.f, 0.f};

    float outacc[8][4];
#pragma unroll
    for (int nt = 0; nt < 8; ++nt)
#pragma unroll
        for (int q = 0; q < 4; ++q) outacc[nt][q] = 0.f;

    const uint32_t qoff = (uint32_t)((w * 16 + (q8 & 1) * 8 + r8) * 144 + (q8 >> 1) * 16);
    uint32_t koffs[8];
#pragma unroll
    for (int p = 0; p < 8; ++p)
        koffs[p] = (uint32_t)((p * 16 + (q8 >> 1) * 8 + r8) * 144 + (q8 & 1) * 16);
    uint32_t voffs[4];
#pragma unroll
    for (int p = 0; p < 4; ++p)
        voffs[p] = (uint32_t)((p * 16 + (q8 >> 1) * 8 + r8) * 272 + (q8 & 1) * 16);

    for (int kt = 0; kt <= qt; ++kt) {
        CP_WAIT(0);
        __syncthreads();
        if (kt < qt) {
            load_kv(kt + 1, (kt + 1) & 1);
            CP_COMMIT();
        }

        const uint32_t kbh = sb + FA_K0 + (uint32_t)((kt & 1) * FA_KST);
        const uint32_t kbl = kbh + FA_QL;

        float acc[16][4];
#pragma unroll
        for (int nt = 0; nt < 16; ++nt)
#pragma unroll
            for (int q = 0; q < 4; ++q) acc[nt][q] = 0.f;

#pragma unroll
        for (int ks = 0; ks < 4; ++ks) {
            const uint32_t ko = (uint32_t)(ks * 32);
            uint32_t ah[4], al[4];
            LDSM_X4(ah, sb + qoff + ko);
            LDSM_X4(al, sb + FA_QL + qoff + ko);
#pragma unroll
            for (int p = 0; p < 8; ++p) {
                uint32_t bhf[4], blf[4];
                LDSM_X4(bhf, kbh + koffs[p] + ko);
                LDSM_X4(blf, kbl + koffs[p] + ko);
                mma16816(acc[2 * p],     ah, &bhf[0]);
                mma16816(acc[2 * p + 1], ah, &bhf[2]);
                mma16816(acc[2 * p],     ah, &blf[0]);
                mma16816(acc[2 * p + 1], ah, &blf[2]);
                mma16816(acc[2 * p],     al, &bhf[0]);
                mma16816(acc[2 * p + 1], al, &bhf[2]);
            }
        }

        const bool diag = (kt == qt);
        const int r0 = w * 16 + lr;
#pragma unroll
        for (int nt = 0; nt < 16; ++nt) {
#pragma unroll
            for (int q = 0; q < 4; ++q) {
                float v = acc[nt][q] * 0.125f;
                if (diag) {
                    int rl = r0 + ((q >= 2) ? 8 : 0);
                    int cl2 = nt * 8 + lc * 2 + (q & 1);
                    if (cl2 > rl) v = -INFINITY;
                }
                acc[nt][q] = v;
            }
            float* p0 = attn_bh + (size_t)(qt * 128 + r0) * Sc + kt * 128 + nt * 8 + lc * 2;
            *(float2*)p0 = make_float2(acc[nt][0], acc[nt][1]);
            *(float2*)(p0 + 8 * Sc) = make_float2(acc[nt][2], acc[nt][3]);
        }

        float nmr[2], fr[2];
#pragma unroll
        for (int r = 0; r < 2; ++r) {
            float tm = -INFINITY;
#pragma unroll
            for (int nt = 0; nt < 16; ++nt)
                tm = fmaxf(tm, fmaxf(acc[nt][r * 2], acc[nt][r * 2 + 1]));
            tm = fmaxf(tm, __shfl_xor_sync(0xffffffffu, tm, 1));
            tm = fmaxf(tm, __shfl_xor_sync(0xffffffffu, tm, 2));
            float nm = fmaxf(m_run[r], tm);
            nmr[r] = nm;
            fr[r]  = __expf(m_run[r] - nm);
            m_run[r] = nm;
        }
#pragma unroll
        for (int nt = 0; nt < 8; ++nt) {
            outacc[nt][0] *= fr[0]; outacc[nt][1] *= fr[0];
            outacc[nt][2] *= fr[1]; outacc[nt][3] *= fr[1];
        }
#pragma unroll
        for (int nt = 0; nt < 16; ++nt) {
            acc[nt][0] = __expf(acc[nt][0] - nmr[0]);
            acc[nt][1] = __expf(acc[nt][1] - nmr[0]);
            acc[nt][2] = __expf(acc[nt][2] - nmr[1]);
            acc[nt][3] = __expf(acc[nt][3] - nmr[1]);
        }
#pragma unroll
        for (int r = 0; r < 2; ++r) {
            float sl = 0.f;
#pragma unroll
            for (int nt = 0; nt < 16; ++nt)
                sl += acc[nt][r * 2] + acc[nt][r * 2 + 1];
            sl += __shfl_xor_sync(0xffffffffu, sl, 1);
            sl += __shfl_xor_sync(0xffffffffu, sl, 2);
            s_run[r] = s_run[r] * fr[r] + sl;
        }

        const uint32_t vHb = sb + FA_V0 + (uint32_t)((kt & 1) * FA_VST);
        const uint32_t vLb = vHb + FA_VL;
#pragma unroll
        for (int ks = 0; ks < 8; ++ks) {
            uint32_t pa_h[4], pa_l[4];
            const float* A0 = acc[2 * ks];
            const float* A1 = acc[2 * ks + 1];
            pa_h[0] = pack_bf16(A0[0], A0[1]);
            pa_h[1] = pack_bf16(A0[2], A0[3]);
            pa_h[2] = pack_bf16(A1[0], A1[1]);
            pa_h[3] = pack_bf16(A1[2], A1[3]);
            {
                __nv_bfloat162 t0 = *(__nv_bfloat162*)&pa_h[0];
                __nv_bfloat162 t1 = *(__nv_bfloat162*)&pa_h[1];
                __nv_bfloat162 t2 = *(__nv_bfloat162*)&pa_h[2];
                __nv_bfloat162 t3 = *(__nv_bfloat162*)&pa_h[3];
                pa_l[0] = pack_bf16(A0[0] - __bfloat162float(t0.x), A0[1] - __bfloat162float(t0.y));
                pa_l[1] = pack_bf16(A0[2] - __bfloat162float(t1.x), A0[3] - __bfloat162float(t1.y));
                pa_l[2] = pack_bf16(A1[0] - __bfloat162float(t2.x), A1[1] - __bfloat162float(t2.y));
                pa_l[3] = pack_bf16(A1[2] - __bfloat162float(t3.x), A1[3] - __bfloat162float(t3.y));
            }
            const uint32_t kov = (uint32_t)(ks * 32);
#pragma unroll
            for (int p = 0; p < 4; ++p) {
                uint32_t vh4[4], vl4[4];
                LDSM_X4(vh4, vHb + voffs[p] + kov);
                LDSM_X4(vl4, vLb + voffs[p] + kov);
                mma16816(outacc[2 * p],     pa_h, &vh4[0]);
                mma16816(outacc[2 * p + 1], pa_h, &vh4[2]);
                mma16816(outacc[2 * p],     pa_h, &vl4[0]);
                mma16816(outacc[2 * p + 1], pa_h, &vl4[2]);
                mma16816(outacc[2 * p],     pa_l, &vh4[0]);
                mma16816(outacc[2 * p + 1], pa_l, &vh4[2]);
            }
        }
    }

    if (lc == 0) {
        int gi0 = qt * 128 + w * 16 + lr;
        rowmax[(size_t)bh * Sc + gi0]     = m_run[0];
        rowsum[(size_t)bh * Sc + gi0]     = s_run[0];
        rowmax[(size_t)bh * Sc + gi0 + 8] = m_run[1];
        rowsum[(size_t)bh * Sc + gi0 + 8] = s_run[1];
    }

    const float inv0 = 1.0f / s_run[0];
    const float inv1 = 1.0f / s_run[1];
#pragma unroll
    for (int nt = 0; nt < 8; ++nt) {
        int gi = qt * 128 + w * 16 + lr;
        size_t base0 = ((size_t)b * Sc + gi) * Dc + h * HS + nt * 8 + lc * 2;
        float v0 = outacc[nt][0] * inv0;
        float v1 = outacc[nt][1] * inv0;
        float v2 = outacc[nt][2] * inv1;
        float v3 = outacc[nt][3] * inv1;
        __nv_bfloat16 h0 = __float2bfloat16(v0);
        __nv_bfloat16 h1 = __float2bfloat16(v1);
        __nv_bfloat16 h2 = __float2bfloat16(v2);
        __nv_bfloat16 h3 = __float2bfloat16(v3);
        __nv_bfloat16 l0 = __float2bfloat16(v0 - __bfloat162float(h0));
        __nv_bfloat16 l1 = __float2bfloat16(v1 - __bfloat162float(h1));
        __nv_bfloat16 l2 = __float2bfloat16(v2 - __bfloat162float(h2));
        __nv_bfloat16 l3 = __float2bfloat16(v3 - __bfloat162float(h3));
        __nv_bfloat162 hp, lp;
        hp.x = h0; hp.y = h1; lp.x = l0; lp.y = l1;
        *(__nv_bfloat162*)(ch + base0) = hp;
        *(__nv_bfloat162*)(cl + base0) = lp;
        hp.x = h2; hp.y = h3; lp.x = l2; lp.y = l3;
        *(__nv_bfloat162*)(ch + base0 + (size_t)8 * Dc) = hp;
        *(__nv_bfloat162*)(cl + base0 + (size_t)8 * Dc) = lp;
    }
}

// ----------------------------------------------------------------------------
// Normalize attn in place (fp32; zeros upper triangle).
// ----------------------------------------------------------------------------
__global__ __launch_bounds__(256) void softmax_norm_kernel(
    float* __restrict__ attn, const float* __restrict__ rowmax,
    const float* __restrict__ rowsum)
{
    size_t i4 = (size_t)blockIdx.x * blockDim.x + threadIdx.x;
    size_t base = i4 * 4;
    int j = (int)(base & (size_t)(Sc - 1));
    size_t row = base >> 11;
    int i = (int)(row & (size_t)(Sc - 1));

    float4* p = (float4*)attn + i4;
    if (j > i) {
        *p = make_float4(0.f, 0.f, 0.f, 0.f);
        return;
    }
    float4 v = *p;
    float mrow = rowmax[row];
    float inv  = 1.0f / rowsum[row];
    float4 o;
    o.x = (j + 0 > i) ? 0.f : __expf(v.x - mrow) * inv;
    o.y = (j + 1 > i) ? 0.f : __expf(v.y - mrow) * inv;
    o.z = (j + 2 > i) ? 0.f : __expf(v.z - mrow) * inv;
    o.w = (j + 3 > i) ? 0.f : __expf(v.w - mrow) * inv;
    *p = o;
}

// ----------------------------------------------------------------------------
// Launch — norm and out-proj run on parallel graph branches (event fork/join).
// Streams/events are created fresh per call (never destroyed: destroying
// capture-participating resources mid-capture would invalidate the graph;
// the few leaked handles are host-side only — no device allocation).
// ----------------------------------------------------------------------------
extern "C" void kernel_launch(void* const* d_in, const int* in_sizes, int n_in,
                              void* d_out, int out_size)
{
    const float* x     = (const float*)d_in[0];
    const float* w_in  = (const float*)d_in[1];
    const float* b_in  = (const float*)d_in[2];
    const float* w_out = (const float*)d_in[3];
    const float* b_out = (const float*)d_in[4];
    float* out = (float*)d_out;

    float *qkv, *rmax, *rsum, *attn_scratch;
    cudaGetSymbolAddress((void**)&qkv,  g_qkv);
    cudaGetSymbolAddress((void**)&rmax, g_rowmax);
    cudaGetSymbolAddress((void**)&rsum, g_rowsum);
    cudaGetSymbolAddress((void**)&attn_scratch, g_attn);

    __nv_bfloat16 *xh, *xl, *wih, *wil, *ch, *cl, *woh, *wol;
    __nv_bfloat16 *qkvh, *qkvl, *vth, *vtl;
    cudaGetSymbolAddress((void**)&xh,  g_xh);
    cudaGetSymbolAddress((void**)&xl,  g_xl);
    cudaGetSymbolAddress((void**)&wih, g_wih);
    cudaGetSymbolAddress((void**)&wil, g_wil);
    cudaGetSymbolAddress((void**)&ch,  g_ch);
    cudaGetSymbolAddress((void**)&cl,  g_cl);
    cudaGetSymbolAddress((void**)&woh, g_woh);
    cudaGetSymbolAddress((void**)&wol, g_wol);
    cudaGetSymbolAddress((void**)&qkvh, g_qkvh);
    cudaGetSymbolAddress((void**)&qkvl, g_qkvl);
    cudaGetSymbolAddress((void**)&vth, g_vth);
    cudaGetSymbolAddress((void**)&vtl, g_vtl);

    const size_t out_elems  = (size_t)Bc * Sc * Dc;
    const size_t attn_elems = (size_t)Bc * Hc * Sc * Sc;
    float* attn = ((size_t)out_size >= out_elems + attn_elems) ? (out + out_elems)
                                                               : attn_scratch;

    cudaFuncSetAttribute(hmma_gemm_bias, cudaFuncAttributeMaxDynamicSharedMemorySize, HG_SMEM);
    cudaFuncSetAttribute(attn_fused_hmma, cudaFuncAttributeMaxDynamicSharedMemorySize, FA_SMEM);

    // Splits of inputs
    {
        int n4 = (Mrows * Dc) / 4;
        split_bf16_kernel<<<(n4 + 255) / 256, 256>>>((const float4*)x,
            (__nv_bfloat162*)xh, (__nv_bfloat162*)xl, n4);
        n4 = (3 * Dc * Dc) / 4;
        split_bf16_kernel<<<(n4 + 255) / 256, 256>>>((const float4*)w_in,
            (__nv_bfloat162*)wih, (__nv_bfloat162*)wil, n4);
        n4 = (Dc * Dc) / 4;
        split_bf16_kernel<<<(n4 + 255) / 256, 256>>>((const float4*)w_out,
            (__nv_bfloat162*)woh, (__nv_bfloat162*)wol, n4);
    }

    // 1) QKV projection (epilogue emits qkvh/qkvl)
    {
        dim3 g((3 * Dc) / 128, Mrows / 128);
        hmma_gemm_bias<<<g, 256, HG_SMEM>>>(xh, xl, wih, wil, b_in, qkv,
                                            qkvh, qkvl, Mrows, 3 * Dc, Dc);
    }

    // 2) Transpose V
    {
        dim3 gt(Sc / 64, Bc * Hc);
        vt_transpose_kernel<<<gt, 256>>>(qkv, vth, vtl);
    }

    // 3) Fused flash attention: raw attn, (m,s), ch/cl
    dim3 g2(Sc / 128, Bc * Hc);
    attn_fused_hmma<<<g2, 256, FA_SMEM>>>(qkvh, qkvl, vth, vtl,
                                          attn, rmax, rsum, ch, cl);

    // 4) Parallel branches: normalize (side stream) || out-proj (main stream)
    cudaStream_t s1;
    cudaEvent_t evFork, evJoin;
    bool forked = (cudaStreamCreateWithFlags(&s1, cudaStreamNonBlocking) == cudaSuccess) &&
                  (cudaEventCreateWithFlags(&evFork, cudaEventDisableTiming) == cudaSuccess) &&
                  (cudaEventCreateWithFlags(&evJoin, cudaEventDisableTiming) == cudaSuccess) &&
                  (cudaEventRecord(evFork, 0) == cudaSuccess) &&
                  (cudaStreamWaitEvent(s1, evFork, 0) == cudaSuccess);

    unsigned nblk = (unsigned)(attn_elems / 4 / 256);
    if (forked) {
        softmax_norm_kernel<<<nblk, 256, 0, s1>>>(attn, rmax, rsum);
        cudaEventRecord(evJoin, s1);
    } else {
        softmax_norm_kernel<<<nblk, 256>>>(attn, rmax, rsum);
    }

    // out-proj on the main stream (concurrent with norm when forked)
    {
        dim3 g(Dc / 128, Mrows / 128);
        hmma_gemm_bias<<<g, 256, HG_SMEM>>>(ch, cl, woh, wol, b_out, out,
                                            nullptr, nullptr, Mrows, Dc, Dc);
    }

    if (forked) {
        cudaStreamWaitEvent(0, evJoin, 0);   // join branches before returning
    }
}